// round 15
// baseline (speedup 1.0000x reference)
#include <cuda_runtime.h>
#include <cstdint>

#define H 4096
#define E 8
#define H4 1024                 // float4 per row
#define TPB 256
#define ITERS (H4 / TPB)        // 4

__device__ unsigned long long g_best;  // (sortable_logit << 32) | (7 - e)
__device__ int g_rcnt;
__device__ int g_idx;

__device__ __forceinline__ unsigned int f2sortable(float f) {
    unsigned int u = __float_as_uint(f);
    return (u & 0x80000000u) ? ~u : (u | 0x80000000u);
}

// ---- Kernel 1: router, 8 blocks (one expert each); last block decodes + resets.
//      Each block triggers programmatic launch completion after its work.
__global__ void __launch_bounds__(TPB) router_kernel(
        const float* __restrict__ x,
        const float* __restrict__ router_w,
        const float* __restrict__ router_b) {
    const int e    = blockIdx.x;
    const int wid  = threadIdx.x >> 5;
    const int lane = threadIdx.x & 31;
    const float4* x4 = (const float4*)x;
    const float4* w4 = (const float4*)(router_w + (size_t)e * H);

    float s = 0.f;
    #pragma unroll
    for (int k = 0; k < ITERS; k++) {
        int i = threadIdx.x + k * TPB;
        float4 a = x4[i];
        float4 b = w4[i];
        s += a.x * b.x + a.y * b.y + a.z * b.z + a.w * b.w;
    }
    #pragma unroll
    for (int o = 16; o > 0; o >>= 1) s += __shfl_xor_sync(0xFFFFFFFFu, s, o);

    __shared__ float s_red[TPB / 32];
    if (lane == 0) s_red[wid] = s;
    __syncthreads();
    if (threadIdx.x == 0) {
        float v = router_b[e];
        #pragma unroll
        for (int w = 0; w < TPB / 32; w++) v += s_red[w];
        unsigned long long key =
            ((unsigned long long)f2sortable(v) << 32) | (unsigned long long)(7 - e);
        atomicMax(&g_best, key);
        __threadfence();
        int r = atomicAdd(&g_rcnt, 1);
        if (r == E - 1) {                      // last router block: decode + reset
            __threadfence();
            unsigned long long b = atomicAdd(&g_best, 0ULL);
            g_idx = 7 - (int)(b & 7ULL);
            g_best = 0ULL;
            g_rcnt = 0;
            __threadfence();
        }
    }
    __syncthreads();
    // All of this block's contribution (and for the last block, g_idx) is
    // globally visible; allow the dependent gate kernel to proceed.
    cudaTriggerProgrammaticLaunchCompletion();
}

// ---- Kernel 2: R2's proven shape — one block per row, 12 front-batched LDGs.
//      PDL: wait for router completion at entry, then run untouched.
__global__ void __launch_bounds__(TPB) gate_mix_kernel(
    const float* __restrict__ x,
    const float* __restrict__ expert_w,
    const float* __restrict__ expert_b,
    const float* __restrict__ gate_w,
    const float* __restrict__ gate_b,
    float* __restrict__ out) {

    // Block until the router grid has triggered completion (g_idx valid).
    cudaGridDependencySynchronize();

    const int row = blockIdx.x;
    const int idx = g_idx;

    const float4* x4 = (const float4*)x;
    const float4* e4 = (const float4*)(expert_w + ((size_t)idx * H + row) * H);
    const float4* g4 = (const float4*)(gate_w + (size_t)row * H);

    // Batch all 12 loads up front (independent -> high MLP)
    float4 xa[ITERS], ea[ITERS], ga[ITERS];
    #pragma unroll
    for (int k = 0; k < ITERS; k++) {
        int i = threadIdx.x + k * TPB;
        xa[k] = x4[i];
        ea[k] = e4[i];
        ga[k] = g4[i];
    }

    float se = 0.f, sg = 0.f;
    #pragma unroll
    for (int k = 0; k < ITERS; k++) {
        se += xa[k].x * ea[k].x + xa[k].y * ea[k].y
            + xa[k].z * ea[k].z + xa[k].w * ea[k].w;
        sg += xa[k].x * ga[k].x + xa[k].y * ga[k].y
            + xa[k].z * ga[k].z + xa[k].w * ga[k].w;
    }

    #pragma unroll
    for (int o = 16; o > 0; o >>= 1) {
        se += __shfl_xor_sync(0xFFFFFFFFu, se, o);
        sg += __shfl_xor_sync(0xFFFFFFFFu, sg, o);
    }

    __shared__ float re[TPB / 32], rg[TPB / 32];
    const int wid  = threadIdx.x >> 5;
    const int lane = threadIdx.x & 31;
    if (lane == 0) { re[wid] = se; rg[wid] = sg; }
    __syncthreads();

    if (threadIdx.x == 0) {
        float SE = 0.f, SG = 0.f;
        #pragma unroll
        for (int w = 0; w < TPB / 32; w++) { SE += re[w]; SG += rg[w]; }
        float mix = tanhf(SE + expert_b[(size_t)idx * H + row]);
        float z = SG + gate_b[row];
        float g = 1.f / (1.f + expf(-z));
        float xv = x[row];
        out[row] = g * mix + (1.f - g) * xv;
    }
}

extern "C" void kernel_launch(void* const* d_in, const int* in_sizes, int n_in,
                              void* d_out, int out_size) {
    const float* x        = (const float*)d_in[0];  // [1, H]
    const float* expert_w = (const float*)d_in[1];  // [E, H, H]
    const float* expert_b = (const float*)d_in[2];  // [E, H]
    const float* router_w = (const float*)d_in[3];  // [E, H]
    const float* router_b = (const float*)d_in[4];  // [E]
    const float* gate_w   = (const float*)d_in[5];  // [H, H]
    const float* gate_b   = (const float*)d_in[6];  // [H]
    float* out = (float*)d_out;                     // [1, H]

    router_kernel<<<E, TPB>>>(x, router_w, router_b);

    // Programmatic dependent launch: gate kernel's launch/setup overlaps the
    // router; the device-side griddepcontrol.wait provides the ordering.
    cudaLaunchConfig_t cfg = {};
    cfg.gridDim  = dim3(H, 1, 1);
    cfg.blockDim = dim3(TPB, 1, 1);
    cfg.dynamicSmemBytes = 0;
    cudaLaunchAttribute attr[1];
    attr[0].id = cudaLaunchAttributeProgrammaticStreamSerialization;
    attr[0].val.programmaticStreamSerializationAllowed = 1;
    cfg.attrs = attr;
    cfg.numAttrs = 1;
    cudaLaunchKernelEx(&cfg, gate_mix_kernel,
                       x, expert_w, expert_b, gate_w, gate_b, out);
}

// round 16
// speedup vs baseline: 1.0088x; 1.0088x over previous
#include <cuda_runtime.h>
#include <cstdint>

#define H 4096
#define E 8
#define H4 1024                 // float4 per row
#define TPB 256
#define ITERS (H4 / TPB)        // 4

__device__ unsigned long long g_best;  // (sortable_logit << 32) | (7 - e)
__device__ int g_rcnt;
__device__ int g_idx;

__device__ __forceinline__ unsigned int f2sortable(float f) {
    unsigned int u = __float_as_uint(f);
    return (u & 0x80000000u) ? ~u : (u | 0x80000000u);
}

// ---- Kernel 1: router, 8 blocks (one expert each); last block decodes + resets,
//      then every block triggers programmatic completion of the gate kernel.
__global__ void __launch_bounds__(TPB) router_kernel(
        const float* __restrict__ x,
        const float* __restrict__ router_w,
        const float* __restrict__ router_b) {
    const int e    = blockIdx.x;
    const int wid  = threadIdx.x >> 5;
    const int lane = threadIdx.x & 31;
    const float4* x4 = (const float4*)x;
    const float4* w4 = (const float4*)(router_w + (size_t)e * H);

    float s = 0.f;
    #pragma unroll
    for (int k = 0; k < ITERS; k++) {
        int i = threadIdx.x + k * TPB;
        float4 a = x4[i];
        float4 b = w4[i];
        s += a.x * b.x + a.y * b.y + a.z * b.z + a.w * b.w;
    }
    #pragma unroll
    for (int o = 16; o > 0; o >>= 1) s += __shfl_xor_sync(0xFFFFFFFFu, s, o);

    __shared__ float s_red[TPB / 32];
    if (lane == 0) s_red[wid] = s;
    __syncthreads();
    if (threadIdx.x == 0) {
        float v = router_b[e];
        #pragma unroll
        for (int w = 0; w < TPB / 32; w++) v += s_red[w];
        unsigned long long key =
            ((unsigned long long)f2sortable(v) << 32) | (unsigned long long)(7 - e);
        atomicMax(&g_best, key);
        __threadfence();
        int r = atomicAdd(&g_rcnt, 1);
        if (r == E - 1) {                      // last router block: decode + reset
            __threadfence();
            unsigned long long b = atomicAdd(&g_best, 0ULL);
            g_idx = 7 - (int)(b & 7ULL);
            g_best = 0ULL;
            g_rcnt = 0;
            __threadfence();
        }
    }
    // PDL trigger: gate kernel may pass its griddepcontrol.wait only after
    // ALL router blocks trigger/exit — i.e. after g_idx is published.
    cudaTriggerProgrammaticLaunchCompletion();
}

// ---- Kernel 2: R2 shape; router-independent loads issued BEFORE the PDL wait
//      so gate_w streaming overlaps router execution.
__global__ void __launch_bounds__(TPB) gate_mix_kernel(
    const float* __restrict__ x,
    const float* __restrict__ expert_w,
    const float* __restrict__ expert_b,
    const float* __restrict__ gate_w,
    const float* __restrict__ gate_b,
    float* __restrict__ out) {

    const int row = blockIdx.x;

    const float4* x4 = (const float4*)x;
    const float4* g4 = (const float4*)(gate_w + (size_t)row * H);

    // Phase A: 8 router-independent loads, in flight before the wait.
    float4 xa[ITERS], ga[ITERS];
    #pragma unroll
    for (int k = 0; k < ITERS; k++) {
        int i = threadIdx.x + k * TPB;
        xa[k] = x4[i];
        ga[k] = g4[i];
    }

    // Wait for router grid (no-op once router has completed; only the first
    // wave pays, and its gate loads are already streaming).
    cudaGridDependencySynchronize();
    const int idx = g_idx;

    // Phase B: expert loads.
    const float4* e4 = (const float4*)(expert_w + ((size_t)idx * H + row) * H);
    float4 ea[ITERS];
    #pragma unroll
    for (int k = 0; k < ITERS; k++) {
        int i = threadIdx.x + k * TPB;
        ea[k] = e4[i];
    }

    float se = 0.f, sg = 0.f;
    #pragma unroll
    for (int k = 0; k < ITERS; k++) {
        sg += xa[k].x * ga[k].x + xa[k].y * ga[k].y
            + xa[k].z * ga[k].z + xa[k].w * ga[k].w;
        se += xa[k].x * ea[k].x + xa[k].y * ea[k].y
            + xa[k].z * ea[k].z + xa[k].w * ea[k].w;
    }

    #pragma unroll
    for (int o = 16; o > 0; o >>= 1) {
        se += __shfl_xor_sync(0xFFFFFFFFu, se, o);
        sg += __shfl_xor_sync(0xFFFFFFFFu, sg, o);
    }

    __shared__ float re[TPB / 32], rg[TPB / 32];
    const int wid  = threadIdx.x >> 5;
    const int lane = threadIdx.x & 31;
    if (lane == 0) { re[wid] = se; rg[wid] = sg; }
    __syncthreads();

    if (threadIdx.x == 0) {
        float SE = 0.f, SG = 0.f;
        #pragma unroll
        for (int w = 0; w < TPB / 32; w++) { SE += re[w]; SG += rg[w]; }
        float mix = tanhf(SE + expert_b[(size_t)idx * H + row]);
        float z = SG + gate_b[row];
        float g = 1.f / (1.f + expf(-z));
        float xv = x[row];
        out[row] = g * mix + (1.f - g) * xv;
    }
}

extern "C" void kernel_launch(void* const* d_in, const int* in_sizes, int n_in,
                              void* d_out, int out_size) {
    const float* x        = (const float*)d_in[0];  // [1, H]
    const float* expert_w = (const float*)d_in[1];  // [E, H, H]
    const float* expert_b = (const float*)d_in[2];  // [E, H]
    const float* router_w = (const float*)d_in[3];  // [E, H]
    const float* router_b = (const float*)d_in[4];  // [E]
    const float* gate_w   = (const float*)d_in[5];  // [H, H]
    const float* gate_b   = (const float*)d_in[6];  // [H]
    float* out = (float*)d_out;                     // [1, H]

    router_kernel<<<E, TPB>>>(x, router_w, router_b);

    // Programmatic dependent launch: gate kernel launches/loads overlap the
    // router; device-side griddepcontrol.wait provides ordering for g_idx.
    cudaLaunchConfig_t cfg = {};
    cfg.gridDim  = dim3(H, 1, 1);
    cfg.blockDim = dim3(TPB, 1, 1);
    cfg.dynamicSmemBytes = 0;
    cudaLaunchAttribute attr[1];
    attr[0].id = cudaLaunchAttributeProgrammaticStreamSerialization;
    attr[0].val.programmaticStreamSerializationAllowed = 1;
    cfg.attrs = attr;
    cfg.numAttrs = 1;
    cudaLaunchKernelEx(&cfg, gate_mix_kernel,
                       x, expert_w, expert_b, gate_w, gate_b, out);
}